// round 14
// baseline (speedup 1.0000x reference)
#include <cuda_runtime.h>

#define VOCAB 9
#define D     4
#define S     16384
#define NBLK  64

// Packed shared weight layout (121 floats):
#define W_EMB   0
#define W_PROJW 36
#define W_PROJB 52
#define W_FORWW 56
#define W_FORWB 72
#define W_PRJW  76
#define W_PRJB  112
#define W_TOTAL 121

// Self-validating count words: word w holds counters 3w..3w+2 in 15-bit
// fields (global max 16384 < 32767) and an arrive count at bits 45-51.
// A word whose arrive field reads NBLK is final. Zero at load; last
// finishing block resets for graph replays.
__device__ unsigned long long g_w[3];
__device__ unsigned           g_done;

// ---- shared helpers --------------------------------------------------------

__device__ __forceinline__ const float* wsrc(
    int q,
    const float* emb, const float* proj_w, const float* proj_b,
    const float* forw_w, const float* forw_b,
    const float* prj_w, const float* prj_b)
{
    if      (q < W_PROJW) return emb    + (q - W_EMB);
    else if (q < W_PROJB) return proj_w + (q - W_PROJW);
    else if (q < W_FORWW) return proj_b + (q - W_PROJB);
    else if (q < W_FORWB) return forw_w + (q - W_FORWW);
    else if (q < W_PRJW)  return forw_b + (q - W_FORWB);
    else if (q < W_PRJB)  return prj_w  + (q - W_PRJW);
    else                  return prj_b  + (q - W_PRJB);
}

// Table threads (tid < VOCAB): count-independent precompute, poll the 3
// fused words, finish the 9x9 probability table into sp.
__device__ __forceinline__ void table_poll_finish(
    int tid, const float* sw, const float (*h0s)[D], float* sp)
{
    if (tid >= VOCAB) return;

    float hv0 = h0s[tid][0], hv1 = h0s[tid][1],
          hv2 = h0s[tid][2], hv3 = h0s[tid][3];
    float sc[VOCAB];
    float m = -3.4e38f;
    #pragma unroll
    for (int u = 0; u < VOCAB; u++) {
        float s = hv0 * h0s[u][0] + hv1 * h0s[u][1]
                + hv2 * h0s[u][2] + hv3 * h0s[u][3];
        sc[u] = s;
        m = fmaxf(m, s);
    }
    float eu[VOCAB];
    #pragma unroll
    for (int u = 0; u < VOCAB; u++)
        eu[u] = __expf(sc[u] - m);

    // poll until every arrive field shows NBLK (co-resident => safe)
    volatile unsigned long long* gw = g_w;
    unsigned long long w0, w1, w2;
    do {
        w0 = gw[0]; w1 = gw[1]; w2 = gw[2];
    } while (((w0 >> 45) & 0x7F) < (unsigned)NBLK ||
             ((w1 >> 45) & 0x7F) < (unsigned)NBLK ||
             ((w2 >> 45) & 0x7F) < (unsigned)NBLK);

    int cu[VOCAB];
    #pragma unroll
    for (int q = 0; q < VOCAB; q++) {
        unsigned long long w = (q < 3) ? w0 : (q < 6) ? w1 : w2;
        cu[q] = (int)((w >> (15 * (q % 3))) & 0x7FFFULL);
    }

    // grouped softmax-weighted sum: attn @ h (exact regrouping by token)
    float wsum = 0.f, a0 = 0.f, a1 = 0.f, a2 = 0.f, a3 = 0.f;
    #pragma unroll
    for (int u = 0; u < VOCAB; u++) {
        float e = eu[u] * (float)cu[u];
        wsum += e;
        a0 += e * h0s[u][0];
        a1 += e * h0s[u][1];
        a2 += e * h0s[u][2];
        a3 += e * h0s[u][3];
    }
    float inv = 1.0f / wsum;
    float r0 = fmaxf(0.f, a0 * inv), r1 = fmaxf(0.f, a1 * inv);
    float r2 = fmaxf(0.f, a2 * inv), r3 = fmaxf(0.f, a3 * inv);

    float h2[D];
    #pragma unroll
    for (int d = 0; d < D; d++) {
        h2[d] = sw[W_FORWB + d]
              + sw[W_FORWW + d * D + 0] * r0
              + sw[W_FORWW + d * D + 1] * r1
              + sw[W_FORWW + d * D + 2] * r2
              + sw[W_FORWW + d * D + 3] * r3;
    }

    float lg[VOCAB];
    float m2 = -3.4e38f;
    #pragma unroll
    for (int c = 0; c < VOCAB; c++) {
        float a = sw[W_PRJB + c];
        #pragma unroll
        for (int k = 0; k < D; k++)
            a += sw[W_PRJW + c * D + k] * h2[k];
        lg[c] = a;
        m2 = fmaxf(m2, a);
    }
    float zsum = 0.f;
    #pragma unroll
    for (int c = 0; c < VOCAB; c++) {
        lg[c] = __expf(lg[c] - m2);
        zsum += lg[c];
    }
    float zinv = 1.0f / zsum;
    #pragma unroll
    for (int c = 0; c < VOCAB; c++)
        sp[tid * VOCAB + c] = lg[c] * zinv;
}

// ---------------------------------------------------------------------------
// FAST kernel: launched only when the host PROVES int64 layout
// (in_sizes[0]==32768 => 128KB of 32-bit words). 64x128: probe p4[t]
// covers the whole array (tokens 2t,2t+1 at .x/.z) AND is the scatter
// payload for output rows 2t,2t+1. ONE load latency, no detection.
// ---------------------------------------------------------------------------
__global__ void __launch_bounds__(128) bert_fast64_kernel(
    const int* __restrict__ x32,
    const float* __restrict__ emb,   const float* __restrict__ proj_w,
    const float* __restrict__ proj_b,const float* __restrict__ forw_w,
    const float* __restrict__ forw_b,const float* __restrict__ prj_w,
    const float* __restrict__ prj_b, float2* __restrict__ out2)
{
    __shared__ int   warp_cnt[4][VOCAB];
    __shared__ float sw[W_TOTAL + 7];
    __shared__ float h0s[VOCAB][D];
    __shared__ float sp[VOCAB * VOCAB];

    const int tid  = threadIdx.x;
    const int wid  = tid >> 5;
    const int lane = tid & 31;
    const int t    = blockIdx.x * 128 + tid;      // 0..8191
    const int4* p4 = (const int4*)x32;

    float wreg = 0.f;
    if (tid < W_TOTAL)
        wreg = __ldg(wsrc(tid, emb, proj_w, proj_b, forw_w, forw_b, prj_w, prj_b));

    int4 pr = __ldg(p4 + t);                      // tokens 2t (.x), 2t+1 (.z)

    unsigned long long acc = (1ULL << (7 * pr.x)) + (1ULL << (7 * pr.z));
    #pragma unroll
    for (int q = 0; q < VOCAB; q++) {
        unsigned c  = (unsigned)((acc >> (7 * q)) & 127ULL);
        unsigned ws = __reduce_add_sync(0xffffffffu, c);
        if (lane == 0) warp_cnt[wid][q] = (int)ws;
    }
    if (tid < W_TOTAL) sw[tid] = wreg;
    __syncthreads();                              // B1: warp_cnt, sw

    // post fused words (threads 0..2) — single concurrent atomic round
    if (tid < 3) {
        unsigned long long pack = 1ULL << 45;
        #pragma unroll
        for (int k = 0; k < 3; k++) {
            int q  = tid * 3 + k;
            int bc = warp_cnt[0][q] + warp_cnt[1][q]
                   + warp_cnt[2][q] + warp_cnt[3][q];
            pack |= (unsigned long long)bc << (15 * k);
        }
        atomicAdd(&g_w[tid], pack);
    }

    // h0 (threads 32..67, off the posting warp)
    if (tid >= 32 && tid < 32 + VOCAB * D) {
        int q = tid - 32;
        int vv = q / D, d = q % D;
        float a = sw[W_PROJB + d];
        #pragma unroll
        for (int k = 0; k < D; k++)
            a += sw[W_EMB + vv * D + k] * sw[W_PROJW + d * D + k];
        h0s[vv][d] = a;
    }
    __syncthreads();                              // B2: h0s

    table_poll_finish(tid, sw, h0s, sp);
    __syncthreads();                              // B3: sp

    // overlap reset chain with scatter: atomic issued, return consumed later
    unsigned done_r = 0xFFFFFFFFu;
    if (tid == 0) done_r = atomicAdd(&g_done, 1u);

    // scatter rows 2t, 2t+1: 18 floats = 9 aligned float2
    float2* o = out2 + (size_t)t * 9;
    const int v0 = pr.x, v1 = pr.z;
    #pragma unroll
    for (int k = 0; k < 9; k++) {
        int i0 = 2 * k, i1 = 2 * k + 1;
        float2 f;
        f.x = sp[((i0 < 9) ? v0 : v1) * VOCAB + (i0 < 9 ? i0 : i0 - 9)];
        f.y = sp[((i1 < 9) ? v0 : v1) * VOCAB + (i1 < 9 ? i1 : i1 - 9)];
        o[k] = f;
    }

    if (tid == 0 && done_r == (unsigned)(NBLK - 1)) {
        g_w[0] = 0ULL; g_w[1] = 0ULL; g_w[2] = 0ULL;
        __threadfence();
        g_done = 0u;
    }
}

// ---------------------------------------------------------------------------
// GENERIC kernel (64x64): warp-local detection (no consensus barrier),
// gated second batch for int64, fused-word posting, overlapped reset.
// ---------------------------------------------------------------------------
__global__ void __launch_bounds__(64) bert_fused_kernel(
    const int* __restrict__ x32,
    const float* __restrict__ emb,   const float* __restrict__ proj_w,
    const float* __restrict__ proj_b,const float* __restrict__ forw_w,
    const float* __restrict__ forw_b,const float* __restrict__ prj_w,
    const float* __restrict__ prj_b, float4* __restrict__ out4)
{
    __shared__ int   warp_cnt[2][VOCAB];
    __shared__ float sw[W_TOTAL + 7];
    __shared__ float h0s[VOCAB][D];
    __shared__ float sp[VOCAB * VOCAB];

    const int tid  = threadIdx.x;
    const int wid  = tid >> 5;
    const int lane = tid & 31;
    const int t    = blockIdx.x * 64 + tid;       // 0..4095
    const int4* p4 = (const int4*)x32;

    float wr0 = 0.f, wr1 = 0.f;
    if (tid < W_TOTAL)
        wr0 = __ldg(wsrc(tid, emb, proj_w, proj_b, forw_w, forw_b, prj_w, prj_b));
    if (tid + 64 < W_TOTAL)
        wr1 = __ldg(wsrc(tid + 64, emb, proj_w, proj_b, forw_w, forw_b, prj_w, prj_b));

    int4 pr = __ldg(p4 + t);                      // in-bounds both layouts

    // WARP-LOCAL detection: 64 odd words per warp, fp-prob (1/9)^64 ~ 0.
    bool okb = (pr.y == 0) && (pr.w == 0)
            && ((unsigned)pr.x < VOCAB) && ((unsigned)pr.z < VOCAB);
    const int is64 = (__all_sync(0xffffffffu, okb) != 0);

    unsigned long long acc = (1ULL << (7 * pr.x)) + (1ULL << (7 * pr.z));

    int  vals[4];
    int4 up, pl0, pl1;
    if (is64) {                                   // gated loads, ~15cyc after probe
        up  = __ldg(p4 + 4096 + t);
        pl0 = __ldg(p4 + 2 * t);
        pl1 = __ldg(p4 + 2 * t + 1);
    } else {
        acc += (1ULL << (7 * pr.y)) + (1ULL << (7 * pr.w));
        vals[0] = pr.x; vals[1] = pr.y; vals[2] = pr.z; vals[3] = pr.w;
    }

    // sw store + barrier hidden under the gated-load latency
    if (tid < W_TOTAL)      sw[tid]      = wr0;
    if (tid + 64 < W_TOTAL) sw[tid + 64] = wr1;
    __syncthreads();                              // B1: sw

    // h0 math also overlaps the gated-load latency (threads 0..35)
    if (tid < VOCAB * D) {
        int vv = tid / D, d = tid % D;
        float a = sw[W_PROJB + d];
        #pragma unroll
        for (int k = 0; k < D; k++)
            a += sw[W_EMB + vv * D + k] * sw[W_PROJW + d * D + k];
        h0s[vv][d] = a;
    }

    if (is64) {
        acc += (1ULL << (7 * up.x)) + (1ULL << (7 * up.z));
        vals[0] = pl0.x; vals[1] = pl0.z; vals[2] = pl1.x; vals[3] = pl1.z;
    }

    #pragma unroll
    for (int q = 0; q < VOCAB; q++) {
        unsigned c  = (unsigned)((acc >> (7 * q)) & 127ULL);
        unsigned ws = __reduce_add_sync(0xffffffffu, c);
        if (lane == 0) warp_cnt[wid][q] = (int)ws;
    }
    __syncthreads();                              // B2: warp_cnt, h0s

    if (tid < 3) {
        unsigned long long pack = 1ULL << 45;
        #pragma unroll
        for (int k = 0; k < 3; k++) {
            int q  = tid * 3 + k;
            int bc = warp_cnt[0][q] + warp_cnt[1][q];
            pack |= (unsigned long long)bc << (15 * k);
        }
        atomicAdd(&g_w[tid], pack);
    }

    table_poll_finish(tid, sw, h0s, sp);
    __syncthreads();                              // B3: sp

    unsigned done_r = 0xFFFFFFFFu;
    if (tid == 0) done_r = atomicAdd(&g_done, 1u);

    float4* o = out4 + (size_t)t * 9;
    #pragma unroll
    for (int k = 0; k < 9; k++) {
        float4 f;
        f.x = sp[vals[(4 * k + 0) / 9] * VOCAB + (4 * k + 0) % 9];
        f.y = sp[vals[(4 * k + 1) / 9] * VOCAB + (4 * k + 1) % 9];
        f.z = sp[vals[(4 * k + 2) / 9] * VOCAB + (4 * k + 2) % 9];
        f.w = sp[vals[(4 * k + 3) / 9] * VOCAB + (4 * k + 3) % 9];
        o[k] = f;
    }

    if (tid == 0 && done_r == (unsigned)(NBLK - 1)) {
        g_w[0] = 0ULL; g_w[1] = 0ULL; g_w[2] = 0ULL;
        __threadfence();
        g_done = 0u;
    }
}

extern "C" void kernel_launch(void* const* d_in, const int* in_sizes, int n_in,
                              void* d_out, int out_size)
{
    const int*   x      = (const int*)d_in[0];
    const float* emb    = (const float*)d_in[1];
    const float* proj_w = (const float*)d_in[2];
    const float* proj_b = (const float*)d_in[3];
    const float* forw_w = (const float*)d_in[4];
    const float* forw_b = (const float*)d_in[5];
    const float* prj_w  = (const float*)d_in[6];
    const float* prj_b  = (const float*)d_in[7];

    if (in_sizes[0] == 2 * S) {
        // 32768 32-bit elements = 128KB => provably int64 layout.
        bert_fast64_kernel<<<NBLK, 128>>>(x, emb, proj_w, proj_b,
                                          forw_w, forw_b, prj_w, prj_b,
                                          (float2*)d_out);
    } else {
        bert_fused_kernel<<<NBLK, 64>>>(x, emb, proj_w, proj_b,
                                        forw_w, forw_b, prj_w, prj_b,
                                        (float4*)d_out);
    }
    (void)n_in; (void)out_size;
}